// round 5
// baseline (speedup 1.0000x reference)
#include <cuda_runtime.h>
#include <math_constants.h>

#define NN    10000
#define EE    160000
#define ET    170000   // EE + NN self loops
#define SNAP  16       // B*T
#define TT    8
#define BB    2
#define CIN   64
#define CC    32

// ---------------- static device scratch ----------------
__device__ float g_xl[NN * SNAP * CC];       // [n][s][c]
__device__ float g_xr[NN * SNAP * CC];       // [n][s][c]
__device__ float g_ee[ET * CC];              // [edge][c]
__device__ float g_loop_sum[NN * 3];
__device__ float g_loop_cnt[NN];
__device__ int   g_cursor[NN];
__device__ int   g_csr_off[NN + 1];
__device__ int   g_csr_src[ET];
__device__ int   g_csr_eid[ET];

// ---------------- prep kernels ----------------

__global__ void k_zero() {
    int i = blockIdx.x * blockDim.x + threadIdx.x;
    if (i < NN) {
        g_loop_cnt[i] = 0.f;
        g_cursor[i] = 0;
        g_loop_sum[i * 3 + 0] = 0.f;
        g_loop_sum[i * 3 + 1] = 0.f;
        g_loop_sum[i * 3 + 2] = 0.f;
    }
}

__global__ void k_deg(const int* __restrict__ ei, const float* __restrict__ ea) {
    int e = blockIdx.x * blockDim.x + threadIdx.x;
    if (e >= EE) return;
    int dst = ei[EE + e];
    atomicAdd(&g_loop_sum[dst * 3 + 0], ea[e * 3 + 0]);
    atomicAdd(&g_loop_sum[dst * 3 + 1], ea[e * 3 + 1]);
    atomicAdd(&g_loop_sum[dst * 3 + 2], ea[e * 3 + 2]);
    atomicAdd(&g_loop_cnt[dst], 1.f);
}

// single-block scan: 1024 threads, 10 items each, one-sync shfl scan
__global__ void k_scan() {
    __shared__ int warp_sums[32];
    int tid = threadIdx.x, lane = tid & 31, wid = tid >> 5;
    int base = tid * 10;
    int v[10];
    int s = 0;
#pragma unroll
    for (int k = 0; k < 10; k++) {
        int idx = base + k;
        int val = (idx < NN) ? ((int)g_loop_cnt[idx] + 1) : 0;
        v[k] = s;
        s += val;
    }
    int incl = s;
#pragma unroll
    for (int o = 1; o < 32; o <<= 1) {
        int u = __shfl_up_sync(0xffffffffu, incl, o);
        if (lane >= o) incl += u;
    }
    if (lane == 31) warp_sums[wid] = incl;
    __syncthreads();
    if (tid < 32) {
        int w = warp_sums[tid];
#pragma unroll
        for (int o = 1; o < 32; o <<= 1) {
            int u = __shfl_up_sync(0xffffffffu, w, o);
            if (tid >= o) w += u;
        }
        warp_sums[tid] = w;
    }
    __syncthreads();
    int warp_off = (wid == 0) ? 0 : warp_sums[wid - 1];
    int thr_excl = warp_off + incl - s;
#pragma unroll
    for (int k = 0; k < 10; k++) {
        int idx = base + k;
        if (idx < NN) g_csr_off[idx] = thr_excl + v[k];
    }
    if (tid == 0) g_csr_off[NN] = warp_sums[31];
}

__global__ void k_scatter(const int* __restrict__ ei) {
    int e = blockIdx.x * blockDim.x + threadIdx.x;
    if (e < EE) {
        int src = ei[e];
        int dst = ei[EE + e];
        int pos = g_csr_off[dst] + atomicAdd(&g_cursor[dst], 1);
        g_csr_src[pos] = src;
        g_csr_eid[pos] = e;
    } else if (e < EE + NN) {
        int n = e - EE;
        int pos = g_csr_off[n + 1] - 1;  // self-loop in the last slot
        g_csr_src[pos] = n;
        g_csr_eid[pos] = EE + n;
    }
}

// ee[r][c] = attr_r @ W_e (self-loop rows: segment mean of incoming attr)
__global__ void k_ee(const float* __restrict__ edge_attr, const float* __restrict__ W_e) {
    int idx = blockIdx.x * blockDim.x + threadIdx.x;
    int r = idx >> 5, c = idx & 31;
    if (r >= ET) return;
    float a0, a1, a2;
    if (r < EE) {
        a0 = edge_attr[r * 3 + 0];
        a1 = edge_attr[r * 3 + 1];
        a2 = edge_attr[r * 3 + 2];
    } else {
        int n = r - EE;
        float cnt = fmaxf(g_loop_cnt[n], 1.f);
        float inv = 1.f / cnt;
        a0 = g_loop_sum[n * 3 + 0] * inv;
        a1 = g_loop_sum[n * 3 + 1] * inv;
        a2 = g_loop_sum[n * 3 + 2] * inv;
    }
    g_ee[r * 32 + c] = a0 * W_e[c] + a1 * W_e[32 + c] + a2 * W_e[64 + c];
}

// Persistent xl/xr transform; packed {Wl,Wr} float2 smem; 2 rows/warp/iter.
__global__ void __launch_bounds__(256) k_xlr(const float* __restrict__ x,
                      const float* __restrict__ W_l, const float* __restrict__ b_l,
                      const float* __restrict__ W_r, const float* __restrict__ b_r) {
    __shared__ float2 sW[CIN * CC];
    int tid = threadIdx.x;
    for (int i = tid; i < CIN * CC; i += 256)
        sW[i] = make_float2(W_l[i], W_r[i]);
    __syncthreads();
    int lane = tid & 31;
    float bl = b_l[lane], br = b_r[lane];
    int gw = blockIdx.x * 8 + (tid >> 5);
    int stride = gridDim.x * 8 * 2;
    for (int r0 = gw * 2; r0 < SNAP * NN; r0 += stride) {
        const float* xp = x + (long)r0 * CIN;
        float a_x0 = xp[lane], a_x1 = xp[lane + 32];
        float b_x0 = xp[CIN + lane], b_x1 = xp[CIN + lane + 32];
        float al_a = 0.f, ar_a = 0.f, al_b = 0.f, ar_b = 0.f;
#pragma unroll
        for (int k = 0; k < CIN; k++) {
            float xa = (k < 32) ? __shfl_sync(0xffffffffu, a_x0, k)
                                : __shfl_sync(0xffffffffu, a_x1, k - 32);
            float xb = (k < 32) ? __shfl_sync(0xffffffffu, b_x0, k)
                                : __shfl_sync(0xffffffffu, b_x1, k - 32);
            float2 w = sW[k * 32 + lane];
            al_a += xa * w.x; ar_a += xa * w.y;
            al_b += xb * w.x; ar_b += xb * w.y;
        }
        int s0 = r0 / NN, n0 = r0 - s0 * NN;
        int r1 = r0 + 1;
        int s1 = r1 / NN, n1 = r1 - s1 * NN;
        g_xl[(n0 * SNAP + s0) * 32 + lane] = al_a + bl;
        g_xr[(n0 * SNAP + s0) * 32 + lane] = ar_a + br;
        g_xl[(n1 * SNAP + s1) * 32 + lane] = al_b + bl;
        g_xr[(n1 * SNAP + s1) * 32 + lane] = ar_b + br;
    }
}

// Fused GATv2 + GRU, warp = (node, batch-half).
// GAT: each warp covers 8 snapshots (1KB gathers: 2 LDG.128/lane/edge),
// lane l = (snapshot-subgroup g=l>>3, channel-quarter q=l&7), pipelined.
// GRU: the warp's 8 snapshots ARE its GRU sequence; smem transpose then
// lane = channel, one recurrence per warp.
__global__ void __launch_bounds__(256, 3) k_gatgru(
        const float* __restrict__ att, const float* __restrict__ bias_gat,
        const float* __restrict__ W_ih, const float* __restrict__ W_hh,
        const float* __restrict__ b_ih, const float* __restrict__ b_hh,
        float* __restrict__ out) {
    __shared__ float2 sW[3][32][32];   // [gate][h][c] = {W_ih, W_hh}
    __shared__ float  sb[6][32];
    __shared__ float  s_tr[8][8][32];  // [warp][s_half][c]

    int tid = threadIdx.x;
    for (int i = tid; i < 3 * 32 * 32; i += 256) {
        int row = i >> 5, h = i & 31;       // row = g*32+c
        int g = row >> 5, c = row & 31;
        sW[g][h][c] = make_float2(W_ih[i], W_hh[i]);
    }
    if (tid < 96) {
        int g = tid >> 5, c = tid & 31;
        sb[g][c] = b_ih[tid];
        sb[3 + g][c] = b_hh[tid];
    }
    __syncthreads();

    int w = tid >> 5, lane = tid & 31;
    int n = blockIdx.x * 4 + (w >> 1);     // grid = NN/4 exact
    int half = w & 1;                      // batch b
    int q = lane & 7, g = lane >> 3;
    int base = (n * SNAP + half * 8) * 32; // this half's 1KB block

    const float4 at4 = *(const float4*)(att + 4 * q);

    float4 xr4[2];
    {
        const float4* p = (const float4*)(g_xr + base);
#pragma unroll
        for (int k = 0; k < 2; k++) xr4[k] = p[k * 32 + lane];
    }

    float4 acc[2];
    acc[0] = make_float4(0.f, 0.f, 0.f, 0.f);
    acc[1] = make_float4(0.f, 0.f, 0.f, 0.f);
    float ssum[2] = {0.f, 0.f};

    int off = g_csr_off[n], end = g_csr_off[n + 1];  // end > off (self-loop)

    // prime pipeline
    float4 a[2], ev;
    {
        int src = g_csr_src[off], eid = g_csr_eid[off];
        const float4* xp = (const float4*)(g_xl + (src * SNAP + half * 8) * 32);
        ev = *(const float4*)(g_ee + eid * 32 + 4 * q);
        a[0] = xp[lane];
        a[1] = xp[32 + lane];
    }

    for (int j = off; j < end; j++) {
        int jn = (j + 1 < end) ? j + 1 : j;
        int src_n = g_csr_src[jn], eid_n = g_csr_eid[jn];
        const float4* xpn = (const float4*)(g_xl + (src_n * SNAP + half * 8) * 32);
        float4 evn = *(const float4*)(g_ee + eid_n * 32 + 4 * q);
        float4 an0 = xpn[lane];
        float4 an1 = xpn[32 + lane];

        float d[2];
#pragma unroll
        for (int k = 0; k < 2; k++) {
            float v0 = a[k].x + ev.x + xr4[k].x;
            float v1 = a[k].y + ev.y + xr4[k].y;
            float v2 = a[k].z + ev.z + xr4[k].z;
            float v3 = a[k].w + ev.w + xr4[k].w;
            v0 = fmaxf(v0, 0.2f * v0);
            v1 = fmaxf(v1, 0.2f * v1);
            v2 = fmaxf(v2, 0.2f * v2);
            v3 = fmaxf(v3, 0.2f * v3);
            d[k] = v0 * at4.x + v1 * at4.y + v2 * at4.z + v3 * at4.w;
        }
#pragma unroll
        for (int o = 1; o < 8; o <<= 1) {
            d[0] += __shfl_xor_sync(0xffffffffu, d[0], o);
            d[1] += __shfl_xor_sync(0xffffffffu, d[1], o);
        }
#pragma unroll
        for (int k = 0; k < 2; k++) {
            float wv = __expf(d[k]);
            ssum[k] += wv;
            acc[k].x += wv * a[k].x;
            acc[k].y += wv * a[k].y;
            acc[k].z += wv * a[k].z;
            acc[k].w += wv * a[k].w;
        }
        a[0] = an0; a[1] = an1; ev = evn;
    }

    const float4 bi4 = *(const float4*)(bias_gat + 4 * q);
#pragma unroll
    for (int k = 0; k < 2; k++) {
        float inv = 1.f / ssum[k];
        int sh = 4 * k + g;                 // s_half within this batch
        float* tp = &s_tr[w][sh][4 * q];
        tp[0] = acc[k].x * inv + bi4.x;
        tp[1] = acc[k].y * inv + bi4.y;
        tp[2] = acc[k].z * inv + bi4.z;
        tp[3] = acc[k].w * inv + bi4.w;
    }
    __syncwarp();

    // ---- GRU: one sequence per warp (batch = half); lane = channel c
    int c = lane;
    float bi0 = sb[0][c], bi1 = sb[1][c], bi2 = sb[2][c];
    float bh0 = sb[3][c], bh1 = sb[4][c], bh2 = sb[5][c];

    float h = 0.f;
    for (int t = 0; t < TT; t++) {
        float ir = bi0, iz = bi1, inn = bi2, hr = bh0, hz = bh1, hn = bh2;
#pragma unroll
        for (int hh = 0; hh < 32; hh++) {
            float xv = s_tr[w][t][hh];      // LDS broadcast
            float hv = __shfl_sync(0xffffffffu, h, hh);
            float2 wr_ = sW[0][hh][c];
            float2 wz_ = sW[1][hh][c];
            float2 wn_ = sW[2][hh][c];
            ir += xv * wr_.x; hr += hv * wr_.y;
            iz += xv * wz_.x; hz += hv * wz_.y;
            inn += xv * wn_.x; hn += hv * wn_.y;
        }
        float r = 1.f / (1.f + __expf(-(ir + hr)));
        float z = 1.f / (1.f + __expf(-(iz + hz)));
        float pre = inn + r * hn;
        float e2 = __expf(-2.f * pre);
        float nn_ = 2.f / (1.f + e2) - 1.f;
        h = (1.f - z) * nn_ + z * h;
        out[((long)(half * TT + t) * NN + n) * 32 + c] = h;
    }
}

// ---------------- launch ----------------
extern "C" void kernel_launch(void* const* d_in, const int* in_sizes, int n_in,
                              void* d_out, int out_size) {
    const float* x        = (const float*)d_in[0];
    const int*   ei       = (const int*)d_in[1];
    const float* eattr    = (const float*)d_in[2];
    const float* W_l      = (const float*)d_in[3];
    const float* b_l      = (const float*)d_in[4];
    const float* W_r      = (const float*)d_in[5];
    const float* b_r      = (const float*)d_in[6];
    const float* W_e      = (const float*)d_in[7];
    const float* att      = (const float*)d_in[8];
    const float* bias_gat = (const float*)d_in[9];
    const float* W_ih     = (const float*)d_in[10];
    const float* W_hh     = (const float*)d_in[11];
    const float* b_ih     = (const float*)d_in[12];
    const float* b_hh     = (const float*)d_in[13];
    float* out = (float*)d_out;

    k_zero<<<(NN + 255) / 256, 256>>>();
    k_deg<<<(EE + 255) / 256, 256>>>(ei, eattr);
    k_scan<<<1, 1024>>>();
    k_scatter<<<(EE + NN + 255) / 256, 256>>>(ei);
    k_ee<<<(ET * 32 + 255) / 256, 256>>>(eattr, W_e);
    k_xlr<<<296, 256>>>(x, W_l, b_l, W_r, b_r);
    k_gatgru<<<NN / 4, 256>>>(att, bias_gat, W_ih, W_hh, b_ih, b_hh, out);
}

// round 6
// speedup vs baseline: 1.2070x; 1.2070x over previous
#include <cuda_runtime.h>
#include <math_constants.h>

#define NN    10000
#define EE    160000
#define ET    170000   // EE + NN self loops
#define SNAP  16       // B*T
#define TT    8
#define BB    2
#define CIN   64
#define CC    32

// ---------------- static device scratch ----------------
__device__ float g_xl[NN * SNAP * CC];       // [n][s][c]
__device__ float g_xr[NN * SNAP * CC];       // [n][s][c]
__device__ float g_ee[ET * CC];              // [edge][c]
__device__ float g_loop_sum[NN * 3];
__device__ float g_loop_cnt[NN];
__device__ int   g_cursor[NN];
__device__ int   g_csr_off[NN + 1];
__device__ int   g_csr_src[ET];
__device__ int   g_csr_eid[ET];

// ---------------- prep kernels ----------------

__global__ void k_zero() {
    int i = blockIdx.x * blockDim.x + threadIdx.x;
    if (i < NN) {
        g_loop_cnt[i] = 0.f;
        g_cursor[i] = 0;
        g_loop_sum[i * 3 + 0] = 0.f;
        g_loop_sum[i * 3 + 1] = 0.f;
        g_loop_sum[i * 3 + 2] = 0.f;
    }
}

__global__ void k_deg(const int* __restrict__ ei, const float* __restrict__ ea) {
    int e = blockIdx.x * blockDim.x + threadIdx.x;
    if (e >= EE) return;
    int dst = ei[EE + e];
    atomicAdd(&g_loop_sum[dst * 3 + 0], ea[e * 3 + 0]);
    atomicAdd(&g_loop_sum[dst * 3 + 1], ea[e * 3 + 1]);
    atomicAdd(&g_loop_sum[dst * 3 + 2], ea[e * 3 + 2]);
    atomicAdd(&g_loop_cnt[dst], 1.f);
}

// single-block scan: 1024 threads, 10 items each, one-sync shfl scan
__global__ void k_scan() {
    __shared__ int warp_sums[32];
    int tid = threadIdx.x, lane = tid & 31, wid = tid >> 5;
    int base = tid * 10;
    int v[10];
    int s = 0;
#pragma unroll
    for (int k = 0; k < 10; k++) {
        int idx = base + k;
        int val = (idx < NN) ? ((int)g_loop_cnt[idx] + 1) : 0;
        v[k] = s;
        s += val;
    }
    int incl = s;
#pragma unroll
    for (int o = 1; o < 32; o <<= 1) {
        int u = __shfl_up_sync(0xffffffffu, incl, o);
        if (lane >= o) incl += u;
    }
    if (lane == 31) warp_sums[wid] = incl;
    __syncthreads();
    if (tid < 32) {
        int w = warp_sums[tid];
#pragma unroll
        for (int o = 1; o < 32; o <<= 1) {
            int u = __shfl_up_sync(0xffffffffu, w, o);
            if (tid >= o) w += u;
        }
        warp_sums[tid] = w;
    }
    __syncthreads();
    int warp_off = (wid == 0) ? 0 : warp_sums[wid - 1];
    int thr_excl = warp_off + incl - s;
#pragma unroll
    for (int k = 0; k < 10; k++) {
        int idx = base + k;
        if (idx < NN) g_csr_off[idx] = thr_excl + v[k];
    }
    if (tid == 0) g_csr_off[NN] = warp_sums[31];
}

__global__ void k_scatter(const int* __restrict__ ei) {
    int e = blockIdx.x * blockDim.x + threadIdx.x;
    if (e < EE) {
        int src = ei[e];
        int dst = ei[EE + e];
        int pos = g_csr_off[dst] + atomicAdd(&g_cursor[dst], 1);
        g_csr_src[pos] = src;
        g_csr_eid[pos] = e;
    } else if (e < EE + NN) {
        int n = e - EE;
        int pos = g_csr_off[n + 1] - 1;  // self-loop in the last slot
        g_csr_src[pos] = n;
        g_csr_eid[pos] = EE + n;
    }
}

// ee[r][c] = attr_r @ W_e (self-loop rows: segment mean of incoming attr)
__global__ void k_ee(const float* __restrict__ edge_attr, const float* __restrict__ W_e) {
    int idx = blockIdx.x * blockDim.x + threadIdx.x;
    int r = idx >> 5, c = idx & 31;
    if (r >= ET) return;
    float a0, a1, a2;
    if (r < EE) {
        a0 = edge_attr[r * 3 + 0];
        a1 = edge_attr[r * 3 + 1];
        a2 = edge_attr[r * 3 + 2];
    } else {
        int n = r - EE;
        float cnt = fmaxf(g_loop_cnt[n], 1.f);
        float inv = 1.f / cnt;
        a0 = g_loop_sum[n * 3 + 0] * inv;
        a1 = g_loop_sum[n * 3 + 1] * inv;
        a2 = g_loop_sum[n * 3 + 2] * inv;
    }
    g_ee[r * 32 + c] = a0 * W_e[c] + a1 * W_e[32 + c] + a2 * W_e[64 + c];
}

// Persistent xl/xr transform; packed {Wl,Wr} float2 smem; 2 rows/warp/iter.
__global__ void __launch_bounds__(256) k_xlr(const float* __restrict__ x,
                      const float* __restrict__ W_l, const float* __restrict__ b_l,
                      const float* __restrict__ W_r, const float* __restrict__ b_r) {
    __shared__ float2 sW[CIN * CC];
    int tid = threadIdx.x;
    for (int i = tid; i < CIN * CC; i += 256)
        sW[i] = make_float2(W_l[i], W_r[i]);
    __syncthreads();
    int lane = tid & 31;
    float bl = b_l[lane], br = b_r[lane];
    int gw = blockIdx.x * 8 + (tid >> 5);
    int stride = gridDim.x * 8 * 2;
    for (int r0 = gw * 2; r0 < SNAP * NN; r0 += stride) {
        const float* xp = x + (long)r0 * CIN;
        float a_x0 = xp[lane], a_x1 = xp[lane + 32];
        float b_x0 = xp[CIN + lane], b_x1 = xp[CIN + lane + 32];
        float al_a = 0.f, ar_a = 0.f, al_b = 0.f, ar_b = 0.f;
#pragma unroll
        for (int k = 0; k < CIN; k++) {
            float xa = (k < 32) ? __shfl_sync(0xffffffffu, a_x0, k)
                                : __shfl_sync(0xffffffffu, a_x1, k - 32);
            float xb = (k < 32) ? __shfl_sync(0xffffffffu, b_x0, k)
                                : __shfl_sync(0xffffffffu, b_x1, k - 32);
            float2 w = sW[k * 32 + lane];
            al_a += xa * w.x; ar_a += xa * w.y;
            al_b += xb * w.x; ar_b += xb * w.y;
        }
        int s0 = r0 / NN, n0 = r0 - s0 * NN;
        int r1 = r0 + 1;
        int s1 = r1 / NN, n1 = r1 - s1 * NN;
        g_xl[(n0 * SNAP + s0) * 32 + lane] = al_a + bl;
        g_xr[(n0 * SNAP + s0) * 32 + lane] = ar_a + br;
        g_xl[(n1 * SNAP + s1) * 32 + lane] = al_b + bl;
        g_xr[(n1 * SNAP + s1) * 32 + lane] = ar_b + br;
    }
}

// Fused GATv2 + GRU: warp per node (round-4 structure), ping-pong 2x unrolled
// edge loop with distance-1 prefetch (no register-copy per edge).
__global__ void __launch_bounds__(256) k_gatgru(
        const float* __restrict__ att, const float* __restrict__ bias_gat,
        const float* __restrict__ W_ih, const float* __restrict__ W_hh,
        const float* __restrict__ b_ih, const float* __restrict__ b_hh,
        float* __restrict__ out) {
    __shared__ float4 sWA[32][32];     // [h][c] = {wi_r, wh_r, wi_z, wh_z}
    __shared__ float2 sWB[32][32];     // [h][c] = {wi_n, wh_n}
    __shared__ float  sb[6][32];
    __shared__ float  s_tr[8][16][32]; // per-warp transpose [warp][s][c]

    int tid = threadIdx.x;
    for (int i = tid; i < 1024; i += 256) {
        int c = i & 31, hh = i >> 5;
        sWA[hh][c] = make_float4(W_ih[c * 32 + hh],        W_hh[c * 32 + hh],
                                 W_ih[(32 + c) * 32 + hh], W_hh[(32 + c) * 32 + hh]);
        sWB[hh][c] = make_float2(W_ih[(64 + c) * 32 + hh], W_hh[(64 + c) * 32 + hh]);
    }
    if (tid < 96) {
        int g = tid >> 5, c = tid & 31;
        sb[g][c] = b_ih[tid];
        sb[3 + g][c] = b_hh[tid];
    }
    __syncthreads();

    int w = tid >> 5, lane = tid & 31;
    int n = blockIdx.x * 8 + w;            // grid = NN/8 exact
    int q = lane & 7, g = lane >> 3;

    const float4 at4 = *(const float4*)(att + 4 * q);

    float4 xr4[4];
    {
        const float4* p = (const float4*)(g_xr + n * SNAP * 32);
#pragma unroll
        for (int k = 0; k < 4; k++) xr4[k] = p[k * 32 + lane];
    }

    float4 acc[4];
#pragma unroll
    for (int k = 0; k < 4; k++) acc[k] = make_float4(0.f, 0.f, 0.f, 0.f);
    float ssum[4] = {0.f, 0.f, 0.f, 0.f};

    int off = g_csr_off[n], end = g_csr_off[n + 1];  // end > off (self-loop)

    float4 a[4], ev;
    {
        int src = g_csr_src[off], eid = g_csr_eid[off];
        const float4* xp = (const float4*)(g_xl + src * SNAP * 32);
        ev = *(const float4*)(g_ee + eid * 32 + 4 * q);
#pragma unroll
        for (int k = 0; k < 4; k++) a[k] = xp[k * 32 + lane];
    }

#define GAT_EDGE(A, EV, VALID)                                              \
    do {                                                                    \
        float d[4];                                                         \
        _Pragma("unroll")                                                   \
        for (int k = 0; k < 4; k++) {                                       \
            float v0 = A[k].x + EV.x + xr4[k].x;                            \
            float v1 = A[k].y + EV.y + xr4[k].y;                            \
            float v2 = A[k].z + EV.z + xr4[k].z;                            \
            float v3 = A[k].w + EV.w + xr4[k].w;                            \
            v0 = fmaxf(v0, 0.2f * v0);                                      \
            v1 = fmaxf(v1, 0.2f * v1);                                      \
            v2 = fmaxf(v2, 0.2f * v2);                                      \
            v3 = fmaxf(v3, 0.2f * v3);                                      \
            d[k] = v0 * at4.x + v1 * at4.y + v2 * at4.z + v3 * at4.w;       \
        }                                                                   \
        _Pragma("unroll")                                                   \
        for (int o = 1; o < 8; o <<= 1) {                                   \
            _Pragma("unroll")                                               \
            for (int k = 0; k < 4; k++)                                     \
                d[k] += __shfl_xor_sync(0xffffffffu, d[k], o);              \
        }                                                                   \
        _Pragma("unroll")                                                   \
        for (int k = 0; k < 4; k++) {                                       \
            float wv = (VALID) ? __expf(d[k]) : 0.f;                        \
            ssum[k] += wv;                                                  \
            acc[k].x += wv * A[k].x;                                        \
            acc[k].y += wv * A[k].y;                                        \
            acc[k].z += wv * A[k].z;                                        \
            acc[k].w += wv * A[k].w;                                        \
        }                                                                   \
    } while (0)

    for (int j = off; j < end; j += 2) {
        // prefetch edge j+1 (clamped) into the alternate set
        int j1 = (j + 1 < end) ? j + 1 : j;
        int src1 = g_csr_src[j1], eid1 = g_csr_eid[j1];
        const float4* xp1 = (const float4*)(g_xl + src1 * SNAP * 32);
        float4 ev1 = *(const float4*)(g_ee + eid1 * 32 + 4 * q);
        float4 an[4];
#pragma unroll
        for (int k = 0; k < 4; k++) an[k] = xp1[k * 32 + lane];

        GAT_EDGE(a, ev, true);            // edge j always valid

        // prefetch edge j+2 (clamped) back into the primary set
        int j2 = (j + 2 < end) ? j + 2 : end - 1;
        int src2 = g_csr_src[j2], eid2 = g_csr_eid[j2];
        const float4* xp2 = (const float4*)(g_xl + src2 * SNAP * 32);
        ev = *(const float4*)(g_ee + eid2 * 32 + 4 * q);
#pragma unroll
        for (int k = 0; k < 4; k++) a[k] = xp2[k * 32 + lane];

        GAT_EDGE(an, ev1, (j + 1 < end)); // edge j+1 masked
    }
#undef GAT_EDGE

    const float4 bi4 = *(const float4*)(bias_gat + 4 * q);
#pragma unroll
    for (int k = 0; k < 4; k++) {
        float inv = 1.f / ssum[k];
        int s = 4 * k + g;
        float* tp = &s_tr[w][s][4 * q];
        tp[0] = acc[k].x * inv + bi4.x;
        tp[1] = acc[k].y * inv + bi4.y;
        tp[2] = acc[k].z * inv + bi4.z;
        tp[3] = acc[k].w * inv + bi4.w;
    }
    __syncwarp();

    // ---- GRU phase: lane = channel c; 2 sequences (b=0 -> s=t, b=1 -> s=8+t)
    int c = lane;
    float bi0 = sb[0][c], bi1 = sb[1][c], bi2 = sb[2][c];
    float bh0 = sb[3][c], bh1 = sb[4][c], bh2 = sb[5][c];

    float h0 = 0.f, h1 = 0.f;
    for (int t = 0; t < TT; t++) {
        float ir0 = bi0, iz0 = bi1, in0 = bi2, hr0 = bh0, hz0 = bh1, hn0 = bh2;
        float ir1 = bi0, iz1 = bi1, in1 = bi2, hr1 = bh0, hz1 = bh1, hn1 = bh2;
#pragma unroll
        for (int hh = 0; hh < 32; hh++) {
            float xv0 = s_tr[w][t][hh];
            float xv1 = s_tr[w][8 + t][hh];
            float hv0 = __shfl_sync(0xffffffffu, h0, hh);
            float hv1 = __shfl_sync(0xffffffffu, h1, hh);
            float4 wA = sWA[hh][c];
            float2 wB = sWB[hh][c];
            ir0 += xv0 * wA.x; hr0 += hv0 * wA.y;
            iz0 += xv0 * wA.z; hz0 += hv0 * wA.w;
            in0 += xv0 * wB.x; hn0 += hv0 * wB.y;
            ir1 += xv1 * wA.x; hr1 += hv1 * wA.y;
            iz1 += xv1 * wA.z; hz1 += hv1 * wA.w;
            in1 += xv1 * wB.x; hn1 += hv1 * wB.y;
        }
        {
            float r = 1.f / (1.f + __expf(-(ir0 + hr0)));
            float z = 1.f / (1.f + __expf(-(iz0 + hz0)));
            float pre = in0 + r * hn0;
            float e2 = __expf(-2.f * pre);
            float nn_ = 2.f / (1.f + e2) - 1.f;
            h0 = (1.f - z) * nn_ + z * h0;
            out[((long)t * NN + n) * 32 + c] = h0;
        }
        {
            float r = 1.f / (1.f + __expf(-(ir1 + hr1)));
            float z = 1.f / (1.f + __expf(-(iz1 + hz1)));
            float pre = in1 + r * hn1;
            float e2 = __expf(-2.f * pre);
            float nn_ = 2.f / (1.f + e2) - 1.f;
            h1 = (1.f - z) * nn_ + z * h1;
            out[((long)(TT + t) * NN + n) * 32 + c] = h1;
        }
    }
}

// ---------------- launch (forked-stream capture for prep concurrency) ----------------
extern "C" void kernel_launch(void* const* d_in, const int* in_sizes, int n_in,
                              void* d_out, int out_size) {
    const float* x        = (const float*)d_in[0];
    const int*   ei       = (const int*)d_in[1];
    const float* eattr    = (const float*)d_in[2];
    const float* W_l      = (const float*)d_in[3];
    const float* b_l      = (const float*)d_in[4];
    const float* W_r      = (const float*)d_in[5];
    const float* b_r      = (const float*)d_in[6];
    const float* W_e      = (const float*)d_in[7];
    const float* att      = (const float*)d_in[8];
    const float* bias_gat = (const float*)d_in[9];
    const float* W_ih     = (const float*)d_in[10];
    const float* W_hh     = (const float*)d_in[11];
    const float* b_ih     = (const float*)d_in[12];
    const float* b_hh     = (const float*)d_in[13];
    float* out = (float*)d_out;

    static cudaStream_t s1 = nullptr, s2 = nullptr;
    static cudaEvent_t eRoot = nullptr, eDeg = nullptr, eXlr = nullptr, eEe = nullptr;
    if (s1 == nullptr) {
        cudaStreamCreateWithFlags(&s1, cudaStreamNonBlocking);
        cudaStreamCreateWithFlags(&s2, cudaStreamNonBlocking);
        cudaEventCreateWithFlags(&eRoot, cudaEventDisableTiming);
        cudaEventCreateWithFlags(&eDeg, cudaEventDisableTiming);
        cudaEventCreateWithFlags(&eXlr, cudaEventDisableTiming);
        cudaEventCreateWithFlags(&eEe, cudaEventDisableTiming);
    }

    // branch 1: xlr depends only on inputs
    cudaEventRecord(eRoot, 0);
    cudaStreamWaitEvent(s1, eRoot, 0);
    k_xlr<<<296, 256, 0, s1>>>(x, W_l, b_l, W_r, b_r);
    cudaEventRecord(eXlr, s1);

    // main: CSR chain
    k_zero<<<(NN + 255) / 256, 256>>>();
    k_deg<<<(EE + 255) / 256, 256>>>(ei, eattr);
    cudaEventRecord(eDeg, 0);

    // branch 2: ee depends only on deg
    cudaStreamWaitEvent(s2, eDeg, 0);
    k_ee<<<(ET * 32 + 255) / 256, 256, 0, s2>>>(eattr, W_e);
    cudaEventRecord(eEe, s2);

    k_scan<<<1, 1024>>>();
    k_scatter<<<(EE + NN + 255) / 256, 256>>>(ei);

    // join
    cudaStreamWaitEvent(0, eXlr, 0);
    cudaStreamWaitEvent(0, eEe, 0);
    k_gatgru<<<NN / 8, 256>>>(att, bias_gat, W_ih, W_hh, b_ih, b_hh, out);
}

// round 7
// speedup vs baseline: 1.2162x; 1.0076x over previous
#include <cuda_runtime.h>
#include <math_constants.h>

#define NN    10000
#define EE    160000
#define ET    170000   // EE + NN self loops
#define SNAP  16       // B*T
#define TT    8
#define BB    2
#define CIN   64
#define CC    32

// ---------------- static device scratch (zero-initialized at load) ----------------
__device__ float g_xl[NN * SNAP * CC];       // [n][s][c]
__device__ float g_xr[NN * SNAP * CC];       // [n][s][c]
__device__ float g_ee[ET * CC];              // [edge][c]
__device__ float g_loop_sum[NN * 3];
__device__ float g_loop_cnt[NN];
__device__ int   g_cursor[NN];
__device__ int   g_csr_off[NN + 1];
__device__ int   g_csr_src[ET];
__device__ int   g_csr_eid[ET];

// ---------------- prep kernels ----------------
// NOTE: loop_sum/loop_cnt/cursor are zero at entry of every replay: statically
// zero-initialized for the first (correctness) run, and re-zeroed by the
// k_gatgru epilogue of the previous replay thereafter (stream-ordered).

__global__ void k_deg(const int* __restrict__ ei, const float* __restrict__ ea) {
    int e = blockIdx.x * blockDim.x + threadIdx.x;
    if (e >= EE) return;
    int dst = ei[EE + e];
    atomicAdd(&g_loop_sum[dst * 3 + 0], ea[e * 3 + 0]);
    atomicAdd(&g_loop_sum[dst * 3 + 1], ea[e * 3 + 1]);
    atomicAdd(&g_loop_sum[dst * 3 + 2], ea[e * 3 + 2]);
    atomicAdd(&g_loop_cnt[dst], 1.f);
}

// single-block scan: 1024 threads, 10 items each, one-sync shfl scan
__global__ void k_scan() {
    __shared__ int warp_sums[32];
    int tid = threadIdx.x, lane = tid & 31, wid = tid >> 5;
    int base = tid * 10;
    int v[10];
    int s = 0;
#pragma unroll
    for (int k = 0; k < 10; k++) {
        int idx = base + k;
        int val = (idx < NN) ? ((int)g_loop_cnt[idx] + 1) : 0;
        v[k] = s;
        s += val;
    }
    int incl = s;
#pragma unroll
    for (int o = 1; o < 32; o <<= 1) {
        int u = __shfl_up_sync(0xffffffffu, incl, o);
        if (lane >= o) incl += u;
    }
    if (lane == 31) warp_sums[wid] = incl;
    __syncthreads();
    if (tid < 32) {
        int w = warp_sums[tid];
#pragma unroll
        for (int o = 1; o < 32; o <<= 1) {
            int u = __shfl_up_sync(0xffffffffu, w, o);
            if (tid >= o) w += u;
        }
        warp_sums[tid] = w;
    }
    __syncthreads();
    int warp_off = (wid == 0) ? 0 : warp_sums[wid - 1];
    int thr_excl = warp_off + incl - s;
#pragma unroll
    for (int k = 0; k < 10; k++) {
        int idx = base + k;
        if (idx < NN) g_csr_off[idx] = thr_excl + v[k];
    }
    if (tid == 0) g_csr_off[NN] = warp_sums[31];
}

__global__ void k_scatter(const int* __restrict__ ei) {
    int e = blockIdx.x * blockDim.x + threadIdx.x;
    if (e < EE) {
        int src = ei[e];
        int dst = ei[EE + e];
        int pos = g_csr_off[dst] + atomicAdd(&g_cursor[dst], 1);
        g_csr_src[pos] = src;
        g_csr_eid[pos] = e;
    } else if (e < EE + NN) {
        int n = e - EE;
        int pos = g_csr_off[n + 1] - 1;  // self-loop in the last slot
        g_csr_src[pos] = n;
        g_csr_eid[pos] = EE + n;
    }
}

// ee[r][c] = attr_r @ W_e (self-loop rows: segment mean of incoming attr)
// One thread computes a float4 of output channels.
__global__ void k_ee(const float* __restrict__ edge_attr, const float* __restrict__ W_e) {
    int idx = blockIdx.x * blockDim.x + threadIdx.x;
    int r = idx >> 3, c4 = idx & 7;
    if (r >= ET) return;
    float a0, a1, a2;
    if (r < EE) {
        a0 = edge_attr[r * 3 + 0];
        a1 = edge_attr[r * 3 + 1];
        a2 = edge_attr[r * 3 + 2];
    } else {
        int n = r - EE;
        float cnt = fmaxf(g_loop_cnt[n], 1.f);
        float inv = 1.f / cnt;
        a0 = g_loop_sum[n * 3 + 0] * inv;
        a1 = g_loop_sum[n * 3 + 1] * inv;
        a2 = g_loop_sum[n * 3 + 2] * inv;
    }
    const float4* We4 = (const float4*)W_e;
    float4 w0 = We4[c4], w1 = We4[8 + c4], w2 = We4[16 + c4];
    float4 o;
    o.x = a0 * w0.x + a1 * w1.x + a2 * w2.x;
    o.y = a0 * w0.y + a1 * w1.y + a2 * w2.y;
    o.z = a0 * w0.z + a1 * w1.z + a2 * w2.z;
    o.w = a0 * w0.w + a1 * w1.w + a2 * w2.w;
    ((float4*)g_ee)[r * 8 + c4] = o;
}

// Persistent xl/xr transform; packed {Wl,Wr} float2 smem; 2 rows/warp/iter.
__global__ void __launch_bounds__(256) k_xlr(const float* __restrict__ x,
                      const float* __restrict__ W_l, const float* __restrict__ b_l,
                      const float* __restrict__ W_r, const float* __restrict__ b_r) {
    __shared__ float2 sW[CIN * CC];
    int tid = threadIdx.x;
    for (int i = tid; i < CIN * CC; i += 256)
        sW[i] = make_float2(W_l[i], W_r[i]);
    __syncthreads();
    int lane = tid & 31;
    float bl = b_l[lane], br = b_r[lane];
    int gw = blockIdx.x * 8 + (tid >> 5);
    int stride = gridDim.x * 8 * 2;
    for (int r0 = gw * 2; r0 < SNAP * NN; r0 += stride) {
        const float* xp = x + (long)r0 * CIN;
        float a_x0 = xp[lane], a_x1 = xp[lane + 32];
        float b_x0 = xp[CIN + lane], b_x1 = xp[CIN + lane + 32];
        float al_a = 0.f, ar_a = 0.f, al_b = 0.f, ar_b = 0.f;
#pragma unroll
        for (int k = 0; k < CIN; k++) {
            float xa = (k < 32) ? __shfl_sync(0xffffffffu, a_x0, k)
                                : __shfl_sync(0xffffffffu, a_x1, k - 32);
            float xb = (k < 32) ? __shfl_sync(0xffffffffu, b_x0, k)
                                : __shfl_sync(0xffffffffu, b_x1, k - 32);
            float2 w = sW[k * 32 + lane];
            al_a += xa * w.x; ar_a += xa * w.y;
            al_b += xb * w.x; ar_b += xb * w.y;
        }
        int s0 = r0 / NN, n0 = r0 - s0 * NN;
        int r1 = r0 + 1;
        int s1 = r1 / NN, n1 = r1 - s1 * NN;
        g_xl[(n0 * SNAP + s0) * 32 + lane] = al_a + bl;
        g_xr[(n0 * SNAP + s0) * 32 + lane] = ar_a + br;
        g_xl[(n1 * SNAP + s1) * 32 + lane] = al_b + bl;
        g_xr[(n1 * SNAP + s1) * 32 + lane] = ar_b + br;
    }
}

// Fused GATv2 + GRU: warp per node, ping-pong 2x unrolled edge loop.
// __launch_bounds__(256,2): cap at 128 regs -> 2 blocks/SM (16 warps).
__global__ void __launch_bounds__(256, 2) k_gatgru(
        const float* __restrict__ att, const float* __restrict__ bias_gat,
        const float* __restrict__ W_ih, const float* __restrict__ W_hh,
        const float* __restrict__ b_ih, const float* __restrict__ b_hh,
        float* __restrict__ out) {
    __shared__ float4 sWA[32][32];     // [h][c] = {wi_r, wh_r, wi_z, wh_z}
    __shared__ float2 sWB[32][32];     // [h][c] = {wi_n, wh_n}
    __shared__ float  sb[6][32];
    __shared__ float  s_tr[8][16][32]; // per-warp transpose [warp][s][c]

    int tid = threadIdx.x;
    for (int i = tid; i < 1024; i += 256) {
        int c = i & 31, hh = i >> 5;
        sWA[hh][c] = make_float4(W_ih[c * 32 + hh],        W_hh[c * 32 + hh],
                                 W_ih[(32 + c) * 32 + hh], W_hh[(32 + c) * 32 + hh]);
        sWB[hh][c] = make_float2(W_ih[(64 + c) * 32 + hh], W_hh[(64 + c) * 32 + hh]);
    }
    if (tid < 96) {
        int g = tid >> 5, c = tid & 31;
        sb[g][c] = b_ih[tid];
        sb[3 + g][c] = b_hh[tid];
    }
    __syncthreads();

    int w = tid >> 5, lane = tid & 31;
    int n = blockIdx.x * 8 + w;            // grid = NN/8 exact
    int q = lane & 7, g = lane >> 3;

    const float4 at4 = *(const float4*)(att + 4 * q);

    float4 xr4[4];
    {
        const float4* p = (const float4*)(g_xr + n * SNAP * 32);
#pragma unroll
        for (int k = 0; k < 4; k++) xr4[k] = p[k * 32 + lane];
    }

    float4 acc[4];
#pragma unroll
    for (int k = 0; k < 4; k++) acc[k] = make_float4(0.f, 0.f, 0.f, 0.f);
    float ssum[4] = {0.f, 0.f, 0.f, 0.f};

    int off = g_csr_off[n], end = g_csr_off[n + 1];  // end > off (self-loop)

    float4 a[4], ev;
    {
        int src = g_csr_src[off], eid = g_csr_eid[off];
        const float4* xp = (const float4*)(g_xl + src * SNAP * 32);
        ev = *(const float4*)(g_ee + eid * 32 + 4 * q);
#pragma unroll
        for (int k = 0; k < 4; k++) a[k] = xp[k * 32 + lane];
    }

#define GAT_EDGE(A, EV, VALID)                                              \
    do {                                                                    \
        float d[4];                                                         \
        _Pragma("unroll")                                                   \
        for (int k = 0; k < 4; k++) {                                       \
            float v0 = A[k].x + EV.x + xr4[k].x;                            \
            float v1 = A[k].y + EV.y + xr4[k].y;                            \
            float v2 = A[k].z + EV.z + xr4[k].z;                            \
            float v3 = A[k].w + EV.w + xr4[k].w;                            \
            v0 = fmaxf(v0, 0.2f * v0);                                      \
            v1 = fmaxf(v1, 0.2f * v1);                                      \
            v2 = fmaxf(v2, 0.2f * v2);                                      \
            v3 = fmaxf(v3, 0.2f * v3);                                      \
            d[k] = v0 * at4.x + v1 * at4.y + v2 * at4.z + v3 * at4.w;       \
        }                                                                   \
        _Pragma("unroll")                                                   \
        for (int o = 1; o < 8; o <<= 1) {                                   \
            _Pragma("unroll")                                               \
            for (int k = 0; k < 4; k++)                                     \
                d[k] += __shfl_xor_sync(0xffffffffu, d[k], o);              \
        }                                                                   \
        _Pragma("unroll")                                                   \
        for (int k = 0; k < 4; k++) {                                       \
            float wv = (VALID) ? __expf(d[k]) : 0.f;                        \
            ssum[k] += wv;                                                  \
            acc[k].x += wv * A[k].x;                                        \
            acc[k].y += wv * A[k].y;                                        \
            acc[k].z += wv * A[k].z;                                        \
            acc[k].w += wv * A[k].w;                                        \
        }                                                                   \
    } while (0)

    for (int j = off; j < end; j += 2) {
        int j1 = (j + 1 < end) ? j + 1 : j;
        int src1 = g_csr_src[j1], eid1 = g_csr_eid[j1];
        const float4* xp1 = (const float4*)(g_xl + src1 * SNAP * 32);
        float4 ev1 = *(const float4*)(g_ee + eid1 * 32 + 4 * q);
        float4 an[4];
#pragma unroll
        for (int k = 0; k < 4; k++) an[k] = xp1[k * 32 + lane];

        GAT_EDGE(a, ev, true);

        int j2 = (j + 2 < end) ? j + 2 : end - 1;
        int src2 = g_csr_src[j2], eid2 = g_csr_eid[j2];
        const float4* xp2 = (const float4*)(g_xl + src2 * SNAP * 32);
        ev = *(const float4*)(g_ee + eid2 * 32 + 4 * q);
#pragma unroll
        for (int k = 0; k < 4; k++) a[k] = xp2[k * 32 + lane];

        GAT_EDGE(an, ev1, (j + 1 < end));
    }
#undef GAT_EDGE

    const float4 bi4 = *(const float4*)(bias_gat + 4 * q);
#pragma unroll
    for (int k = 0; k < 4; k++) {
        float inv = 1.f / ssum[k];
        int s = 4 * k + g;
        float* tp = &s_tr[w][s][4 * q];
        tp[0] = acc[k].x * inv + bi4.x;
        tp[1] = acc[k].y * inv + bi4.y;
        tp[2] = acc[k].z * inv + bi4.z;
        tp[3] = acc[k].w * inv + bi4.w;
    }
    __syncwarp();

    // ---- GRU phase: lane = channel c; 2 sequences (b=0 -> s=t, b=1 -> s=8+t)
    int c = lane;
    float bi0 = sb[0][c], bi1 = sb[1][c], bi2 = sb[2][c];
    float bh0 = sb[3][c], bh1 = sb[4][c], bh2 = sb[5][c];

    float h0 = 0.f, h1 = 0.f;
    for (int t = 0; t < TT; t++) {
        float ir0 = bi0, iz0 = bi1, in0 = bi2, hr0 = bh0, hz0 = bh1, hn0 = bh2;
        float ir1 = bi0, iz1 = bi1, in1 = bi2, hr1 = bh0, hz1 = bh1, hn1 = bh2;
#pragma unroll
        for (int hh = 0; hh < 32; hh++) {
            float xv0 = s_tr[w][t][hh];
            float xv1 = s_tr[w][8 + t][hh];
            float hv0 = __shfl_sync(0xffffffffu, h0, hh);
            float hv1 = __shfl_sync(0xffffffffu, h1, hh);
            float4 wA = sWA[hh][c];
            float2 wB = sWB[hh][c];
            ir0 += xv0 * wA.x; hr0 += hv0 * wA.y;
            iz0 += xv0 * wA.z; hz0 += hv0 * wA.w;
            in0 += xv0 * wB.x; hn0 += hv0 * wB.y;
            ir1 += xv1 * wA.x; hr1 += hv1 * wA.y;
            iz1 += xv1 * wA.z; hz1 += hv1 * wA.w;
            in1 += xv1 * wB.x; hn1 += hv1 * wB.y;
        }
        {
            float r = 1.f / (1.f + __expf(-(ir0 + hr0)));
            float z = 1.f / (1.f + __expf(-(iz0 + hz0)));
            float pre = in0 + r * hn0;
            float e2 = __expf(-2.f * pre);
            float nn_ = 2.f / (1.f + e2) - 1.f;
            h0 = (1.f - z) * nn_ + z * h0;
            out[((long)t * NN + n) * 32 + c] = h0;
        }
        {
            float r = 1.f / (1.f + __expf(-(ir1 + hr1)));
            float z = 1.f / (1.f + __expf(-(iz1 + hz1)));
            float pre = in1 + r * hn1;
            float e2 = __expf(-2.f * pre);
            float nn_ = 2.f / (1.f + e2) - 1.f;
            h1 = (1.f - z) * nn_ + z * h1;
            out[((long)(TT + t) * NN + n) * 32 + c] = h1;
        }
    }

    // epilogue: re-zero per-node counters for the NEXT replay (this warp owns n)
    if (lane < 3) g_loop_sum[n * 3 + lane] = 0.f;
    else if (lane == 3) g_loop_cnt[n] = 0.f;
    else if (lane == 4) g_cursor[n] = 0;
}

// ---------------- launch (forked-stream capture for prep concurrency) ----------------
extern "C" void kernel_launch(void* const* d_in, const int* in_sizes, int n_in,
                              void* d_out, int out_size) {
    const float* x        = (const float*)d_in[0];
    const int*   ei       = (const int*)d_in[1];
    const float* eattr    = (const float*)d_in[2];
    const float* W_l      = (const float*)d_in[3];
    const float* b_l      = (const float*)d_in[4];
    const float* W_r      = (const float*)d_in[5];
    const float* b_r      = (const float*)d_in[6];
    const float* W_e      = (const float*)d_in[7];
    const float* att      = (const float*)d_in[8];
    const float* bias_gat = (const float*)d_in[9];
    const float* W_ih     = (const float*)d_in[10];
    const float* W_hh     = (const float*)d_in[11];
    const float* b_ih     = (const float*)d_in[12];
    const float* b_hh     = (const float*)d_in[13];
    float* out = (float*)d_out;

    static cudaStream_t s1 = nullptr, s2 = nullptr;
    static cudaEvent_t eRoot = nullptr, eDeg = nullptr, eXlr = nullptr, eEe = nullptr;
    if (s1 == nullptr) {
        cudaStreamCreateWithFlags(&s1, cudaStreamNonBlocking);
        cudaStreamCreateWithFlags(&s2, cudaStreamNonBlocking);
        cudaEventCreateWithFlags(&eRoot, cudaEventDisableTiming);
        cudaEventCreateWithFlags(&eDeg, cudaEventDisableTiming);
        cudaEventCreateWithFlags(&eXlr, cudaEventDisableTiming);
        cudaEventCreateWithFlags(&eEe, cudaEventDisableTiming);
    }

    // branch 1: xlr depends only on inputs
    cudaEventRecord(eRoot, 0);
    cudaStreamWaitEvent(s1, eRoot, 0);
    k_xlr<<<296, 256, 0, s1>>>(x, W_l, b_l, W_r, b_r);
    cudaEventRecord(eXlr, s1);

    // main: CSR chain (counters pre-zeroed by previous replay's gatgru)
    k_deg<<<(EE + 255) / 256, 256>>>(ei, eattr);
    cudaEventRecord(eDeg, 0);

    // branch 2: ee depends only on deg
    cudaStreamWaitEvent(s2, eDeg, 0);
    k_ee<<<(ET * 8 + 255) / 256, 256, 0, s2>>>(eattr, W_e);
    cudaEventRecord(eEe, s2);

    k_scan<<<1, 1024>>>();
    k_scatter<<<(EE + NN + 255) / 256, 256>>>(ei);

    // join
    cudaStreamWaitEvent(0, eXlr, 0);
    cudaStreamWaitEvent(0, eEe, 0);
    k_gatgru<<<NN / 8, 256>>>(att, bias_gat, W_ih, W_hh, b_ih, b_hh, out);
}